// round 3
// baseline (speedup 1.0000x reference)
#include <cuda_runtime.h>
#include <cstdint>

// Problem constants (fixed by the dataset)
#define HH 128
#define WW 240
#define CC 320
#define NG 40          // groups
#define CPG 8          // channels per group
#define DD 48          // disparity bins
#define PADL 48        // left zero-pad in smem row (>= max d = 47)
#define ROW (WW + PADL)        // 288 words: stride %32 == 0 -> conflict-free for consecutive w
#define GRP_PER_CHUNK 5
#define CH_PER_CHUNK (GRP_PER_CHUNK * CPG)   // 40 channels
#define NCHUNK (NG / GRP_PER_CHUNK)          // 8
#define TPB 256

// ---------------------------------------------------------------------------
// gwc kernel: block = (h, chunk). smem caches 40 tgt channels for the whole
// row (zero-padded left so w<d reads hit zeros -> correct masking for free).
// Each thread owns one w; per group it keeps the 8 ref channels in registers
// (amortized over all 48 disparities) and streams tgt from smem.
// ---------------------------------------------------------------------------
__global__ __launch_bounds__(TPB)
void gwc_kernel(const float* __restrict__ ref, const float* __restrict__ tgt,
                float* __restrict__ out) {
    __shared__ float s[CH_PER_CHUNK * ROW];   // 40*288*4 = 46.08 KB

    const int h = blockIdx.x;
    const int chunk = blockIdx.y;
    const int c0 = chunk * CH_PER_CHUNK;

    // zero the left pad of every smem row
    for (int i = threadIdx.x; i < CH_PER_CHUNK * PADL; i += TPB) {
        int c = i / PADL, p = i % PADL;
        s[c * ROW + p] = 0.0f;
    }
    // fill smem with tgt rows (float4 vectorized; 240 = 60*4, 16B aligned)
    for (int i = threadIdx.x; i < CH_PER_CHUNK * (WW / 4); i += TPB) {
        int c = i / (WW / 4), j = i % (WW / 4);
        float4 v = *(const float4*)(tgt + ((size_t)(c0 + c) * HH + h) * WW + j * 4);
        *(float4*)(s + c * ROW + PADL + j * 4) = v;
    }
    __syncthreads();

    const int w = threadIdx.x;
    if (w >= WW) return;

    for (int g = 0; g < GRP_PER_CHUNK; ++g) {
        // 8 ref channels for this (g, h, w) -> registers, reused for all d
        float r[CPG];
        const float* rp = ref + ((size_t)(c0 + g * CPG) * HH + h) * WW + w;
#pragma unroll
        for (int k = 0; k < CPG; ++k) r[k] = __ldg(rp + (size_t)k * HH * WW);

        const float* sp = s + (g * CPG) * ROW + PADL + w;
        const int outc = chunk * GRP_PER_CHUNK + g;
        float* op = out + ((size_t)outc * DD * HH + h) * WW + w;

#pragma unroll
        for (int d = 0; d < DD; ++d) {
            // two partial sums -> shorter FMA dependency chain
            float a0 = 0.0f, a1 = 0.0f;
#pragma unroll
            for (int k = 0; k < CPG; k += 2) {
                a0 += r[k]     * sp[(k)     * ROW - d];
                a1 += r[k + 1] * sp[(k + 1) * ROW - d];
            }
            op[(size_t)d * HH * WW] = (a0 + a1) * 0.125f;
        }
    }
}

// ---------------------------------------------------------------------------
// concat kernel: out channels 40..51 = ref_concat masked (w>=d),
//                channels 52..63 = tgt_concat shifted right by d (zero fill).
// float4 stores; sources are tiny (1.5 MB each) -> L2 resident.
// ---------------------------------------------------------------------------
__global__ __launch_bounds__(TPB)
void concat_kernel(const float* __restrict__ refc, const float* __restrict__ tgtc,
                   float* __restrict__ out) {
    const int NQ = WW / 4;                       // 60 float4 per row
    int idx = blockIdx.x * TPB + threadIdx.x;
    const int total = 24 * DD * HH * NQ;
    if (idx >= total) return;

    int wq = idx % NQ;  int t = idx / NQ;
    int h  = t % HH;    t /= HH;
    int d  = t % DD;    t /= DD;
    int c  = t;                                  // 0..23
    int wb = wq * 4;

    float4 v;
    if (c < 12) {
        float4 x = *(const float4*)(refc + ((size_t)c * HH + h) * WW + wb);
        v.x = (wb + 0 >= d) ? x.x : 0.0f;
        v.y = (wb + 1 >= d) ? x.y : 0.0f;
        v.z = (wb + 2 >= d) ? x.z : 0.0f;
        v.w = (wb + 3 >= d) ? x.w : 0.0f;
    } else {
        const float* p = tgtc + ((size_t)(c - 12) * HH + h) * WW;
        v.x = (wb + 0 >= d) ? __ldg(p + wb + 0 - d) : 0.0f;
        v.y = (wb + 1 >= d) ? __ldg(p + wb + 1 - d) : 0.0f;
        v.z = (wb + 2 >= d) ? __ldg(p + wb + 2 - d) : 0.0f;
        v.w = (wb + 3 >= d) ? __ldg(p + wb + 3 - d) : 0.0f;
    }
    *(float4*)(out + (((size_t)(NG + c) * DD + d) * HH + h) * WW + wb) = v;
}

extern "C" void kernel_launch(void* const* d_in, const int* in_sizes, int n_in,
                              void* d_out, int out_size) {
    const float* ref_gwc    = (const float*)d_in[0];
    const float* tgt_gwc    = (const float*)d_in[1];
    const float* ref_concat = (const float*)d_in[2];
    const float* tgt_concat = (const float*)d_in[3];
    float* out = (float*)d_out;

    dim3 ggrid(HH, NCHUNK);                      // 128 x 8 = 1024 blocks
    gwc_kernel<<<ggrid, TPB>>>(ref_gwc, tgt_gwc, out);

    const int total = 24 * DD * HH * (WW / 4);   // 8,847,360
    concat_kernel<<<(total + TPB - 1) / TPB, TPB>>>(ref_concat, tgt_concat, out);
}

// round 4
// speedup vs baseline: 1.1465x; 1.1465x over previous
#include <cuda_runtime.h>
#include <cstdint>

// Fixed problem shape
#define HH 128
#define WW 240
#define NG 40          // gwc groups
#define CPG 8          // channels per group
#define DD 48          // disparity bins
#define PADL 48        // left zero pad (>= max d)
#define NPOS (WW + PADL)   // 288 logical positions per smem row
#define ROWA 296           // allocated words per row (288 + max skew 8)
#define TPB 64

#define GWC_BLOCKS (HH * NG)   // 5120
#define CAT_BLOCKS (24 * DD)   // 1152
// Interleave: for bid < 5760, every 5th block (bid%5==4) is a concat block.
#define MIX_LIMIT (CAT_BLOCKS * 5)   // 5760
#define TOTAL_BLOCKS (GWC_BLOCKS + CAT_BLOCKS)  // 6272

// skewed smem index: injective (gap-1 between 32-word segments) and
// bank-conflict-free for lane patterns p = 4*lane + const.
__device__ __forceinline__ int swz(int p) { return p + (p >> 5); }

__global__ __launch_bounds__(TPB, 10)
void fused_kernel(const float* __restrict__ ref, const float* __restrict__ tgt,
                  const float* __restrict__ refc, const float* __restrict__ tgtc,
                  float* __restrict__ out) {
    __shared__ float s[CPG * ROWA];   // 9472 B (used by gwc blocks only)

    const int bid = blockIdx.x;
    const int tid = threadIdx.x;

    // ---- block-id interleaving: spread concat blocks among gwc blocks ----
    bool is_cat;
    int wid_;  // work id within its class
    if (bid < MIX_LIMIT) {
        int q = bid / 5, r = bid - q * 5;
        is_cat = (r == 4);
        wid_ = is_cat ? q : (q * 4 + r);
    } else {
        is_cat = false;
        wid_ = 4 * CAT_BLOCKS + (bid - MIX_LIMIT);   // 4608..5119
    }

    if (!is_cat) {
        // ================= gwc block: one (h, group) =================
        const int g = wid_ % NG;
        const int h = wid_ / NG;

        // fill smem: 8 tgt channel rows, left-padded with zeros, skewed layout
        for (int i = tid; i < CPG * NPOS; i += TPB) {
            int k = i / NPOS, p = i - k * NPOS;
            float v = 0.0f;
            if (p >= PADL)
                v = tgt[(((size_t)(g * CPG + k)) * HH + h) * WW + (p - PADL)];
            s[k * ROWA + swz(p)] = v;
        }
        __syncthreads();

        if (tid < 60) {
            const int w4 = tid * 4;

            // ref registers (x 1/8 folded in), 8 channels x 4 w
            float r[CPG][4];
#pragma unroll
            for (int k = 0; k < CPG; ++k) {
                float4 v = *(const float4*)(ref + (((size_t)(g * CPG + k)) * HH + h) * WW + w4);
                r[k][0] = v.x * 0.125f; r[k][1] = v.y * 0.125f;
                r[k][2] = v.z * 0.125f; r[k][3] = v.w * 0.125f;
            }

            // rolling window: Wb[k][slot] holds tgt value at position p with p&3==slot
            float Wb[CPG][4];
#pragma unroll
            for (int k = 0; k < CPG; ++k)
#pragma unroll
                for (int j = 0; j < 4; ++j) {
                    int p = PADL + w4 + j;          // position for d=0
                    Wb[k][j] = s[k * ROWA + swz(p)]; // slot j == p&3 (w4 % 4 == 0)
                }

            float* op = out + ((size_t)g * DD * HH + h) * WW + w4;

            for (int d4 = 0; d4 < DD; d4 += 4) {
#pragma unroll
                for (int t = 0; t < 4; ++t) {
                    const int d = d4 + t;
                    float a0 = 0.f, a1 = 0.f, a2 = 0.f, a3 = 0.f;
#pragma unroll
                    for (int k = 0; k < CPG; ++k) {
                        a0 += r[k][0] * Wb[k][(0 + 4 - t) & 3];
                        a1 += r[k][1] * Wb[k][(1 + 4 - t) & 3];
                        a2 += r[k][2] * Wb[k][(2 + 4 - t) & 3];
                        a3 += r[k][3] * Wb[k][(3 + 4 - t) & 3];
                    }
                    float4 o; o.x = a0; o.y = a1; o.z = a2; o.w = a3;
                    *(float4*)op = o;
                    op += HH * WW;    // next disparity plane

                    // slide: drop position w4+3-d, load w4-d-1 into same slot
                    int p = PADL + w4 - d - 1;       // >= 0 always (PADL >= d+1)
                    int idx = swz(p);
#pragma unroll
                    for (int k = 0; k < CPG; ++k)
                        Wb[k][(3 + 4 - t) & 3] = s[k * ROWA + idx];
                }
            }
        }
    } else {
        // ================= concat block: one (c, d) plane =================
        const int d = wid_ % DD;
        const int c = wid_ / DD;          // 0..23
        if (tid >= 60) return;
        const int wb = tid * 4;

        float* ob = out + (((size_t)(NG + c) * DD + d) * HH) * WW + wb;
        const bool m0 = (wb + 0 >= d), m1 = (wb + 1 >= d),
                   m2 = (wb + 2 >= d), m3 = (wb + 3 >= d);

        if (c < 12) {
            // masked copy of ref_concat plane
            const float* ib = refc + ((size_t)c * HH) * WW + wb;
#pragma unroll 4
            for (int h = 0; h < HH; ++h) {
                float4 x = *(const float4*)(ib + h * WW);
                float4 v;
                v.x = m0 ? x.x : 0.f;
                v.y = m1 ? x.y : 0.f;
                v.z = m2 ? x.z : 0.f;
                v.w = m3 ? x.w : 0.f;
                *(float4*)(ob + h * WW) = v;
            }
        } else {
            // right-shifted tgt_concat plane (zero fill on left)
            const float* ib = tgtc + ((size_t)(c - 12) * HH) * WW + (wb - d);
#pragma unroll 4
            for (int h = 0; h < HH; ++h) {
                const float* p = ib + h * WW;
                float4 v;
                v.x = m0 ? __ldg(p + 0) : 0.f;
                v.y = m1 ? __ldg(p + 1) : 0.f;
                v.z = m2 ? __ldg(p + 2) : 0.f;
                v.w = m3 ? __ldg(p + 3) : 0.f;
                *(float4*)(ob + h * WW) = v;
            }
        }
    }
}

extern "C" void kernel_launch(void* const* d_in, const int* in_sizes, int n_in,
                              void* d_out, int out_size) {
    const float* ref_gwc    = (const float*)d_in[0];
    const float* tgt_gwc    = (const float*)d_in[1];
    const float* ref_concat = (const float*)d_in[2];
    const float* tgt_concat = (const float*)d_in[3];
    float* out = (float*)d_out;

    fused_kernel<<<TOTAL_BLOCKS, TPB>>>(ref_gwc, tgt_gwc, ref_concat, tgt_concat, out);
}